// round 7
// baseline (speedup 1.0000x reference)
#include <cuda_runtime.h>

#define NB 2
#define NP 524288           // points per batch
#define NG 1024             // oversampled grid per dim
#define NF 512              // frequency grid per dim
#define ROWC 1032           // padded row length in complex (8 wrap columns)
#define ROWF4 516           // padded row length in float4 (2 complex each)
#define NROWA 1032          // allocated rows (1024 + 7 wrap rows, padded)
#define NT 2048             // total tiles: 2 batches x 32x32
#define BETA_F 4.712388980384690f   // 1.5*pi
#define DPI 3.14159265358979323846

// ---------------- static device scratch (no allocations allowed) ----------------
__device__ float2 d_spec[NB * NG * NG];        // row-FFT result (only 512 rows/batch valid)
__device__ float4 d_gE[NB * NROWA * ROWF4];    // even-parity padded copy of g (rows+cols wrapped)
__device__ float4 d_gO[NB * NROWA * ROWF4];    // shifted-by-one padded copy of g
__device__ float  d_cinv[NF];                  // 1 / I0(M*arg) deconvolution coefficients
__device__ float2 d_tw[NG];                    // e^{-2 pi i j / 1024}
__device__ int    d_cnt[NT];                   // per-tile point counts
__device__ int    d_off[NT];                   // exclusive offsets
__device__ int    d_cur[NT];                   // scatter cursors
__device__ float4 d_px[NB * NP];               // binned points: (x, y, bits(p), 0)

// ---------------- init: deconvolution coefficients + twiddles ----------------
__global__ void init_kernel() {
    int t = blockIdx.x * blockDim.x + threadIdx.x;
    if (t < NF) {
        double k   = (double)(t - 256);
        double w   = 2.0 * DPI * k / 1024.0;
        double bet = 1.5 * DPI;
        double arg = sqrt(bet * bet - w * w);
        double x   = 4.0 * arg;                 // M * arg, always >= 17.7
        double tt = 3.75 / x;
        double poly = 0.39894228 + tt*(0.01328592 + tt*(0.00225319 + tt*(-0.00157565 +
                      tt*(0.00916281 + tt*(-0.02057706 + tt*(0.02635537 +
                      tt*(-0.01647633 + tt*0.00392377)))))));
        double i0 = exp(x) / sqrt(x) * poly;
        d_cinv[t] = (float)(1.0 / i0);          // (1024/i0)^2 * (1/1024^2) == (1/i0)^2
    }
    if (t < NG) {
        double th = -2.0 * DPI * (double)t / 1024.0;
        d_tw[t] = make_float2((float)cos(th), (float)sin(th));
    }
}

__device__ __forceinline__ float2 cmulf(float2 a, float2 b) {
    return make_float2(a.x * b.x - a.y * b.y, a.x * b.y + a.y * b.x);
}

// ---------------- fused: deconvolve + ifftshift + 1024-pt row FFT ----------------
__global__ void fft_rows_fused(const float* __restrict__ fhat) {
    __shared__ float2 sA[1024];
    __shared__ float2 sB[1024];
    int bi = blockIdx.x;                  // [0, 1024): 2 batches x 512 nonzero rows
    int b  = bi >> 9;
    int rr = bi & 511;
    int m1 = (rr < 256) ? rr : rr + 512;        // output spectrum row
    int i1 = (rr < 256) ? rr + 256 : rr - 256;  // source fhat row
    float ci1 = d_cinv[i1];
    const float2* fh = (const float2*)fhat + (size_t)(b * 512 + i1) * 512;
    int t = threadIdx.x;                  // 512 threads
#pragma unroll
    for (int h = 0; h < 2; h++) {
        int m2 = t + h * 512;
        float2 v = make_float2(0.0f, 0.0f);
        if (m2 < 256 || m2 >= 768) {
            int i2 = (m2 < 256) ? m2 + 256 : m2 - 768;
            float2 f = fh[i2];
            float s = ci1 * d_cinv[i2];
            v = make_float2(f.x * s, f.y * s);
        }
        sA[m2] = v;
    }
    __syncthreads();
    float2* x = sA;
    float2* y = sB;
#pragma unroll
    for (int k = 0; k < 10; k++) {
        int s  = 1 << k;
        int sp = t & ~(s - 1);
        float2 a  = x[t];
        float2 c  = x[t + 512];
        float2 wp = d_tw[sp];
        float2 sum = make_float2(a.x + c.x, a.y + c.y);
        float2 dif = make_float2(a.x - c.x, a.y - c.y);
        y[t + sp]     = sum;
        y[t + sp + s] = cmulf(dif, wp);
        __syncthreads();
        float2* tmp = x; x = y; y = tmp;
    }
    float2* base = d_spec + (b << 20) + (m1 << 10);
    base[t]       = x[t];
    base[t + 512] = x[t + 512];
}

// ---------------- fused: 4-column 1024-pt FFT + gE/gO epilogue ----------------
__global__ void fft_cols_fused() {
    extern __shared__ float2 sm[];        // [0,4096) = buf A, [4096,8192) = buf B
    float2* x = sm;
    float2* y = sm + 4096;
    int bi = blockIdx.x;                  // [0, 512)
    int b  = bi >> 8;
    int c0 = (bi & 255) << 2;             // 4 columns per block
    int j  = threadIdx.x;                 // 512 threads
    int c  = j & 3;
    int tb = j >> 2;                      // [0, 128)

    const float2* spec = d_spec + (b << 20) + c0 + c;
#pragma unroll
    for (int q = 0; q < 4; q++) {
        int u = tb + (q << 7);            // butterfly index in [0, 512)
        float2 wp = d_tw[u];
        float2 v, s0, s1;
        if (u < 256) {
            v = spec[(size_t)u << 10];
            s0 = v;
            s1 = cmulf(v, wp);
        } else {
            v = spec[(size_t)(u + 512) << 10];
            s0 = v;
            s1 = cmulf(make_float2(-v.x, -v.y), wp);
        }
        x[((2 * u) << 2) + c]     = s0;
        x[((2 * u + 1) << 2) + c] = s1;
    }
    __syncthreads();

#pragma unroll
    for (int k = 1; k < 10; k++) {
        int s = 1 << k;
#pragma unroll
        for (int q = 0; q < 4; q++) {
            int u  = tb + (q << 7);
            int sp = u & ~(s - 1);
            float2 a  = x[(u << 2) + c];
            float2 cc = x[((u + 512) << 2) + c];
            float2 wp = d_tw[sp];
            float2 sum = make_float2(a.x + cc.x, a.y + cc.y);
            float2 dif = make_float2(a.x - cc.x, a.y - cc.y);
            y[((u + sp) << 2) + c]     = sum;
            y[((u + sp + s) << 2) + c] = cmulf(dif, wp);
        }
        __syncthreads();
        float2* tmp = x; x = y; y = tmp;
    }

    // epilogue: padded gather buffers with column wrap (<8 -> +1024) and row wrap
    int t = threadIdx.x;
    int jm1 = (c0 + 1023) & 1023;
    float2* gE2 = (float2*)d_gE + (size_t)b * (NROWA * ROWC);
    float2* gO2 = (float2*)d_gO + (size_t)b * (NROWA * ROWC);
#pragma unroll
    for (int h = 0; h < 2; h++) {
        int r = t + h * 512;
        float2 v0 = x[(r << 2) + 0];
        float2 v1 = x[(r << 2) + 1];
        float2 v2 = x[(r << 2) + 2];
        float2 v3 = x[(r << 2) + 3];
#pragma unroll
        for (int rep = 0; rep < 2; rep++) {
            if (rep == 1 && r >= 7) break;          // row wrap: rows 0..6 -> 1024..1030
            size_t rowb = (size_t)(r + rep * 1024) * ROWC;
            float4* ge4 = (float4*)(gE2 + rowb + c0);
            float4 a0 = make_float4(v0.x, v0.y, v1.x, v1.y);
            float4 a1 = make_float4(v2.x, v2.y, v3.x, v3.y);
            ge4[0] = a0;
            ge4[1] = a1;
            if (c0 < 8) {
                float4* ge4w = (float4*)(gE2 + rowb + 1024 + c0);
                ge4w[0] = a0;
                ge4w[1] = a1;
            }
            gO2[rowb + jm1]    = v0;
            gO2[rowb + c0]     = v1;
            gO2[rowb + c0 + 1] = v2;
            gO2[rowb + c0 + 2] = v3;
            if (jm1 < 8)      gO2[rowb + 1024 + jm1]    = v0;
            if (c0 < 8) {
                gO2[rowb + 1024 + c0]     = v1;
                if (c0 + 1 < 8) gO2[rowb + 1024 + c0 + 1] = v2;
                if (c0 + 2 < 8) gO2[rowb + 1024 + c0 + 2] = v3;
            }
        }
    }
}

// ---------------- Kaiser-Bessel time-domain window (one-sided exp approx) ----------------
__device__ __forceinline__ float kbwin(float s) {
    float u2 = fmaf(-s, s, 16.0f);            // M^2 - s^2
    if (u2 <= 0.0f) return 0.0f;
    float rinv = rsqrtf(u2);                  // 1/u
    float u    = u2 * rinv;
    return __expf(BETA_F * u) * rinv * 0.159154943091895336f;  // e^{bu}/(2 pi u)
}

// ---------------- binning: tile id from point ----------------
__device__ __forceinline__ int point_tile(float2 xy, int p) {
    int l01 = (int)floorf(xy.x * 1024.0f);
    int l02 = (int)floorf(xy.y * 1024.0f);
    int r0 = (l01 - 3) & 1023;
    int c0 = (l02 - 3) & 1023;
    return ((p >> 19) << 10) + ((r0 >> 5) << 5) + (c0 >> 5);
}

__global__ void zero_cnt_kernel() {
    d_cnt[blockIdx.x * 1024 + threadIdx.x] = 0;
}

__global__ void bin_count_kernel(const float* __restrict__ xin) {
    int p = blockIdx.x * blockDim.x + threadIdx.x;
    float2 xy = ((const float2*)xin)[p];
    atomicAdd(&d_cnt[point_tile(xy, p)], 1);
}

__global__ void scan_kernel() {
    __shared__ int sa[NT];
    __shared__ int sb[NT];
    int t = threadIdx.x;                  // 1024 threads
    sa[t]        = d_cnt[t];
    sa[t + 1024] = d_cnt[t + 1024];
    __syncthreads();
    int* cur = sa;
    int* nxt = sb;
#pragma unroll
    for (int st = 1; st < NT; st <<= 1) {
#pragma unroll
        for (int h = 0; h < 2; h++) {
            int k = t + h * 1024;
            nxt[k] = cur[k] + ((k >= st) ? cur[k - st] : 0);
        }
        __syncthreads();
        int* tmp = cur; cur = nxt; nxt = tmp;
    }
#pragma unroll
    for (int h = 0; h < 2; h++) {
        int k = t + h * 1024;
        int e = cur[k] - d_cnt[k];        // exclusive prefix
        d_off[k] = e;
        d_cur[k] = e;
    }
}

__global__ void scatter_kernel(const float* __restrict__ xin) {
    int p = blockIdx.x * blockDim.x + threadIdx.x;
    float2 xy = ((const float2*)xin)[p];
    int pos = atomicAdd(&d_cur[point_tile(xy, p)], 1);
    d_px[pos] = make_float4(xy.x, xy.y, __int_as_float(p), 0.0f);
}

// ---------------- binned gather: one block per 32x32 tile, patches from smem ----------------
__global__ void __launch_bounds__(256) gather_binned(float* __restrict__ out) {
    __shared__ float4 sE[39 * 21];        // tile+halo, even parity (stride 21 float4)
    __shared__ float4 sO[39 * 21];        // odd parity
    int blk = blockIdx.x;                 // [0, NT)
    int b   = blk >> 10;
    int Tr  = ((blk >> 5) & 31) << 5;
    int Tc  = (blk & 31) << 5;
    int tid = threadIdx.x;

    // load 39 rows x 20 float4 from each parity buffer (coalesced)
    const float4* gE4 = d_gE + (size_t)b * (NROWA * ROWF4) + (size_t)Tr * ROWF4 + (Tc >> 1);
    const float4* gO4 = d_gO + (size_t)b * (NROWA * ROWF4) + (size_t)Tr * ROWF4 + (Tc >> 1);
    for (int i = tid; i < 39 * 20; i += 256) {
        int row = i / 20;
        int col = i - row * 20;
        sE[row * 21 + col] = gE4[(size_t)row * ROWF4 + col];
        sO[row * 21 + col] = gO4[(size_t)row * ROWF4 + col];
    }
    __syncthreads();

    int off = d_off[blk];
    int end = off + d_cnt[blk];
    for (int i = off + tid; i < end; i += 256) {
        float4 pt = d_px[i];
        int p = __float_as_int(pt.z);

        float xn1 = pt.x * 1024.0f;
        float fl1 = floorf(xn1);
        int   l01 = (int)fl1;
        float fr1 = xn1 - fl1;

        float xn2 = pt.y * 1024.0f;
        float fl2 = floorf(xn2);
        int   l02 = (int)fl2;
        float fr2 = xn2 - fl2;

        float w1[8], w2[8];
#pragma unroll
        for (int t = 0; t < 8; t++) {
            float o = (float)(t - 3);
            w1[t] = kbwin(fr1 - o);
            w2[t] = kbwin(fr2 - o);
        }

        int r0 = (l01 - 3) & 1023;
        int c0 = (l02 - 3) & 1023;
        int dr = r0 - Tr;                 // [0, 31]
        int q  = (c0 - Tc) >> 1;          // [0, 15] (works for both parities)
        const float4* s = (c0 & 1) ? sO : sE;
        const float4* sp = s + dr * 21 + q;

        float accre = 0.0f, accim = 0.0f;
#pragma unroll
        for (int r = 0; r < 8; r++) {
            float4 a0 = sp[0];
            float4 a1 = sp[1];
            float4 a2 = sp[2];
            float4 a3 = sp[3];
            sp += 21;
            float sre = w2[0]*a0.x + w2[1]*a0.z + w2[2]*a1.x + w2[3]*a1.z
                      + w2[4]*a2.x + w2[5]*a2.z + w2[6]*a3.x + w2[7]*a3.z;
            float sim = w2[0]*a0.y + w2[1]*a0.w + w2[2]*a1.y + w2[3]*a1.w
                      + w2[4]*a2.y + w2[5]*a2.w + w2[6]*a3.y + w2[7]*a3.w;
            accre = fmaf(w1[r], sre, accre);
            accim = fmaf(w1[r], sim, accim);
        }
        ((float2*)out)[p] = make_float2(accre, accim);
    }
}

// ---------------- launch ----------------
extern "C" void kernel_launch(void* const* d_in, const int* in_sizes, int n_in,
                              void* d_out, int out_size) {
    const float* xin = (const float*)d_in[0];   // [B, P, 2]
    const float* fh  = (const float*)d_in[1];   // [B,512,512,2]
    if (n_in >= 2 && in_sizes[0] < in_sizes[1]) {
        const float* t = xin; xin = fh; fh = t;
    }
    cudaFuncSetAttribute(fft_cols_fused,
                         cudaFuncAttributeMaxDynamicSharedMemorySize, 65536);
    init_kernel<<<4, 256>>>();
    zero_cnt_kernel<<<2, 1024>>>();
    bin_count_kernel<<<(NB * NP) / 256, 256>>>(xin);
    fft_rows_fused<<<NB * 512, 512>>>(fh);
    scan_kernel<<<1, 1024>>>();
    scatter_kernel<<<(NB * NP) / 256, 256>>>(xin);
    fft_cols_fused<<<NB * 256, 512, 65536>>>();
    gather_binned<<<NT, 256>>>((float*)d_out);
}

// round 8
// speedup vs baseline: 2.7729x; 2.7729x over previous
#include <cuda_runtime.h>
#include <cuda_fp16.h>

#define NB 2
#define NP 524288           // points per batch
#define NG 1024             // oversampled grid per dim
#define NF 512              // frequency grid per dim
#define ROWC 1032           // padded row length in complex (8 wrap columns)
#define ROWU2 516           // padded row length in uint2 (2 half-complex each)
#define NROWA 1032          // allocated rows (1024 + 7 wrap rows, padded)
#define BETA_F 4.712388980384690f   // 1.5*pi
#define DPI 3.14159265358979323846
// 2^40 grid scale (folded into d_cinv as 2^20 per dimension); exact inverse below
#define INV_SCALE (1.0f / 1099511627776.0f)

// ---------------- static device scratch (no allocations allowed) ----------------
__device__ float2 d_spec[NB * NG * NG];        // row-FFT result (only 512 rows/batch valid)
__device__ uint2  d_gEh[NB * NROWA * ROWU2];   // even-parity half2 grid (rows+cols wrapped)
__device__ uint2  d_gOh[NB * NROWA * ROWU2];   // shifted-by-one half2 grid
__device__ float  d_cinv[NF];                  // 2^20 / I0(M*arg) deconvolution coefficients
__device__ float2 d_tw[NG];                    // e^{-2 pi i j / 1024}

// ---------------- init: deconvolution coefficients + twiddles ----------------
__global__ void init_kernel() {
    int t = blockIdx.x * blockDim.x + threadIdx.x;
    if (t < NF) {
        double k   = (double)(t - 256);
        double w   = 2.0 * DPI * k / 1024.0;
        double bet = 1.5 * DPI;
        double arg = sqrt(bet * bet - w * w);
        double x   = 4.0 * arg;                 // M * arg, always >= 17.7
        double tt = 3.75 / x;
        double poly = 0.39894228 + tt*(0.01328592 + tt*(0.00225319 + tt*(-0.00157565 +
                      tt*(0.00916281 + tt*(-0.02057706 + tt*(0.02635537 +
                      tt*(-0.01647633 + tt*0.00392377)))))));
        double i0 = exp(x) / sqrt(x) * poly;
        d_cinv[t] = (float)(1048576.0 / i0);    // 2^20 per dim -> grid scaled by 2^40
    }
    if (t < NG) {
        double th = -2.0 * DPI * (double)t / 1024.0;
        d_tw[t] = make_float2((float)cos(th), (float)sin(th));
    }
}

__device__ __forceinline__ float2 cmulf(float2 a, float2 b) {
    return make_float2(a.x * b.x - a.y * b.y, a.x * b.y + a.y * b.x);
}

// ---------------- fused: deconvolve + ifftshift + 1024-pt row FFT ----------------
__global__ void fft_rows_fused(const float* __restrict__ fhat) {
    __shared__ float2 sA[1024];
    __shared__ float2 sB[1024];
    int bi = blockIdx.x;                  // [0, 1024): 2 batches x 512 nonzero rows
    int b  = bi >> 9;
    int rr = bi & 511;
    int m1 = (rr < 256) ? rr : rr + 512;        // output spectrum row
    int i1 = (rr < 256) ? rr + 256 : rr - 256;  // source fhat row
    float ci1 = d_cinv[i1];
    const float2* fh = (const float2*)fhat + (size_t)(b * 512 + i1) * 512;
    int t = threadIdx.x;                  // 512 threads
#pragma unroll
    for (int h = 0; h < 2; h++) {
        int m2 = t + h * 512;
        float2 v = make_float2(0.0f, 0.0f);
        if (m2 < 256 || m2 >= 768) {
            int i2 = (m2 < 256) ? m2 + 256 : m2 - 768;
            float2 f = fh[i2];
            float s = ci1 * d_cinv[i2];
            v = make_float2(f.x * s, f.y * s);
        }
        sA[m2] = v;
    }
    __syncthreads();
    float2* x = sA;
    float2* y = sB;
#pragma unroll
    for (int k = 0; k < 10; k++) {
        int s  = 1 << k;
        int sp = t & ~(s - 1);
        float2 a  = x[t];
        float2 c  = x[t + 512];
        float2 wp = d_tw[sp];
        float2 sum = make_float2(a.x + c.x, a.y + c.y);
        float2 dif = make_float2(a.x - c.x, a.y - c.y);
        y[t + sp]     = sum;
        y[t + sp + s] = cmulf(dif, wp);
        __syncthreads();
        float2* tmp = x; x = y; y = tmp;
    }
    float2* base = d_spec + (b << 20) + (m1 << 10);
    base[t]       = x[t];
    base[t + 512] = x[t + 512];
}

// ---------------- fused: 4-column 1024-pt FFT + half2 gE/gO epilogue ----------------
__global__ void fft_cols_fused() {
    extern __shared__ float2 sm[];        // [0,4096) = buf A, [4096,8192) = buf B
    float2* x = sm;
    float2* y = sm + 4096;
    int bi = blockIdx.x;                  // [0, 512)
    int b  = bi >> 8;
    int c0 = (bi & 255) << 2;             // 4 columns per block
    int j  = threadIdx.x;                 // 512 threads
    int c  = j & 3;
    int tb = j >> 2;                      // [0, 128)

    const float2* spec = d_spec + (b << 20) + c0 + c;
#pragma unroll
    for (int q = 0; q < 4; q++) {
        int u = tb + (q << 7);            // butterfly index in [0, 512)
        float2 wp = d_tw[u];
        float2 v, s0, s1;
        if (u < 256) {
            v = spec[(size_t)u << 10];
            s0 = v;
            s1 = cmulf(v, wp);
        } else {
            v = spec[(size_t)(u + 512) << 10];
            s0 = v;
            s1 = cmulf(make_float2(-v.x, -v.y), wp);
        }
        x[((2 * u) << 2) + c]     = s0;
        x[((2 * u + 1) << 2) + c] = s1;
    }
    __syncthreads();

#pragma unroll
    for (int k = 1; k < 10; k++) {
        int s = 1 << k;
#pragma unroll
        for (int q = 0; q < 4; q++) {
            int u  = tb + (q << 7);
            int sp = u & ~(s - 1);
            float2 a  = x[(u << 2) + c];
            float2 cc = x[((u + 512) << 2) + c];
            float2 wp = d_tw[sp];
            float2 sum = make_float2(a.x + cc.x, a.y + cc.y);
            float2 dif = make_float2(a.x - cc.x, a.y - cc.y);
            y[((u + sp) << 2) + c]     = sum;
            y[((u + sp + s) << 2) + c] = cmulf(dif, wp);
        }
        __syncthreads();
        float2* tmp = x; x = y; y = tmp;
    }

    // epilogue: half2 padded gather buffers, column wrap (<8 -> +1024) + row wrap
    int t = threadIdx.x;
    int jm1 = (c0 + 1023) & 1023;         // gO column fed by our c==0 value
    __half2* gEh = (__half2*)d_gEh + (size_t)b * (NROWA * ROWC);
    __half2* gOh = (__half2*)d_gOh + (size_t)b * (NROWA * ROWC);
#pragma unroll
    for (int h = 0; h < 2; h++) {
        int r = t + h * 512;
        __half2 h0 = __float22half2_rn(x[(r << 2) + 0]);
        __half2 h1 = __float22half2_rn(x[(r << 2) + 1]);
        __half2 h2 = __float22half2_rn(x[(r << 2) + 2]);
        __half2 h3 = __float22half2_rn(x[(r << 2) + 3]);
        unsigned u0 = *(unsigned*)&h0;
        unsigned u1 = *(unsigned*)&h1;
        unsigned u2 = *(unsigned*)&h2;
        unsigned u3 = *(unsigned*)&h3;
#pragma unroll
        for (int rep = 0; rep < 2; rep++) {
            if (rep == 1 && r >= 7) break;          // row wrap: rows 0..6 -> 1024..1030
            size_t rowb = (size_t)(r + rep * 1024) * ROWC;
            // gE cols c0..c0+3: one aligned 16B store
            *(uint4*)(gEh + rowb + c0) = make_uint4(u0, u1, u2, u3);
            if (c0 < 8)
                *(uint4*)(gEh + rowb + 1024 + c0) = make_uint4(u0, u1, u2, u3);
            // gO[j] = g[j+1]: aligned pair (c0,c0+1) <- (v1,v2), scalars for v0,v3
            *(uint2*)(gOh + rowb + c0) = make_uint2(u1, u2);
            gOh[rowb + jm1]    = h0;
            gOh[rowb + c0 + 2] = h3;
            if (jm1 < 8) gOh[rowb + 1024 + jm1] = h0;
            if (c0 < 8) {
                *(uint2*)(gOh + rowb + 1024 + c0) = make_uint2(u1, u2);
                gOh[rowb + 1024 + c0 + 2] = h3;     // c0+2 <= 6 < 8 always here
            }
        }
    }
}

// ---------------- Kaiser-Bessel time-domain window (one-sided exp approx) ----------------
__device__ __forceinline__ float kbwin_c(float s, float cst) {
    float u2 = fmaf(-s, s, 16.0f);            // M^2 - s^2
    if (u2 <= 0.0f) return 0.0f;
    float rinv = rsqrtf(u2);                  // 1/u
    float u    = u2 * rinv;
    return __expf(BETA_F * u) * rinv * cst;   // e^{bu}/(2 pi u) * extra scale
}

// ---------------- per-point 8x8 gather: 4 lanes cooperate per point (half2 grid) ----------------
__global__ void __launch_bounds__(256) gather_kernel(const float* __restrict__ xin,
                                                     float* __restrict__ out) {
    int tid  = blockIdx.x * blockDim.x + threadIdx.x;
    int c    = tid & 3;                   // lane's uint2 column within the patch row
    int p    = tid >> 2;                  // point id, [0, NB*NP)
    int b    = p >> 19;
    float2 xy = ((const float2*)xin)[p];

    float xn1 = xy.x * 1024.0f;
    float fl1 = floorf(xn1);
    int   l01 = (int)fl1;
    float fr1 = xn1 - fl1;

    float xn2 = xy.y * 1024.0f;
    float fl2 = floorf(xn2);
    int   l02 = (int)fl2;
    float fr2 = xn2 - fl2;

    // lane c owns taps 2c and 2c+1 of each dimension; w1 carries the 2^-40 unscale
    float o0  = (float)(2 * c - 3);
    float w1a = kbwin_c(fr1 - o0,        0.159154943091895336f * INV_SCALE);
    float w1b = kbwin_c(fr1 - o0 - 1.0f, 0.159154943091895336f * INV_SCALE);
    float w2a = kbwin_c(fr2 - o0,        0.159154943091895336f);
    float w2b = kbwin_c(fr2 - o0 - 1.0f, 0.159154943091895336f);

    // broadcast the 8 row weights across the 4-lane group
    float w1[8];
#pragma unroll
    for (int d = 0; d < 4; d++) {
        w1[2 * d]     = __shfl_sync(0xffffffffu, w1a, d, 4);
        w1[2 * d + 1] = __shfl_sync(0xffffffffu, w1b, d, 4);
    }

    int r0 = (l01 - 3) & 1023;
    int c0 = (l02 - 3) & 1023;
    const uint2* gp = ((c0 & 1) ? d_gOh : d_gEh)
                    + (size_t)b * (NROWA * ROWU2) + (size_t)r0 * ROWU2 + (c0 >> 1) + c;

    float accre = 0.0f, accim = 0.0f;
#pragma unroll
    for (int i = 0; i < 8; i++) {
        uint2 q = __ldg(gp + i * ROWU2);      // constant offsets, 8B per lane
        float2 a0 = __half22float2(*reinterpret_cast<const __half2*>(&q.x));
        float2 a1 = __half22float2(*reinterpret_cast<const __half2*>(&q.y));
        float sre = w2a * a0.x + w2b * a1.x;
        float sim = w2a * a0.y + w2b * a1.y;
        accre = fmaf(w1[i], sre, accre);
        accim = fmaf(w1[i], sim, accim);
    }
    // reduce across the 4 cooperating lanes
    accre += __shfl_xor_sync(0xffffffffu, accre, 1);
    accim += __shfl_xor_sync(0xffffffffu, accim, 1);
    accre += __shfl_xor_sync(0xffffffffu, accre, 2);
    accim += __shfl_xor_sync(0xffffffffu, accim, 2);
    if (c == 0)
        ((float2*)out)[p] = make_float2(accre, accim);
}

// ---------------- launch ----------------
extern "C" void kernel_launch(void* const* d_in, const int* in_sizes, int n_in,
                              void* d_out, int out_size) {
    const float* xin = (const float*)d_in[0];   // [B, P, 2]
    const float* fh  = (const float*)d_in[1];   // [B,512,512,2]
    if (n_in >= 2 && in_sizes[0] < in_sizes[1]) {
        const float* t = xin; xin = fh; fh = t;
    }
    cudaFuncSetAttribute(fft_cols_fused,
                         cudaFuncAttributeMaxDynamicSharedMemorySize, 65536);
    init_kernel<<<4, 256>>>();
    fft_rows_fused<<<NB * 512, 512>>>(fh);
    fft_cols_fused<<<NB * 256, 512, 65536>>>();
    gather_kernel<<<(NB * NP * 4) / 256, 256>>>(xin, (float*)d_out);
}